// round 7
// baseline (speedup 1.0000x reference)
#include <cuda_runtime.h>
#include <math.h>

// ---------------------------------------------------------------------------
// Static device scratch (allocation-free rule). Zero-initialized at load.
// ---------------------------------------------------------------------------
#define MAX_M 50432
#define LC    256      // chunk length for linear G/I scans
#define LSEG  6400     // stitch segment length
#define NSEG  8        // stitch segments (8*6400 = 51200 >= m-1)
#define SUB   1600     // smem staging sub-block within a segment
#define TOTAL (NSEG * LSEG)

__device__ float  d_Sg[MAX_M];
__device__ float  d_Si[MAX_M];
__device__ float  d_Gl[MAX_M];
__device__ float  d_Il[MAX_M];
__device__ float  d_Gfe[256];
__device__ float  d_Ife[256];
__device__ double d_GstD[256];
__device__ double d_IstD[256];
__device__ double d_Ptab[256];
__device__ float4 d_cb4[(TOTAL + 16) / 2];   // float2 view: per-step (c, b)
__device__ float  g_ent[2][16];              // segment entries, ping-pong
__device__ int    g_bar_count;
__device__ int    g_bar_sense;

// ---------------------------------------------------------------------------
// Kernel 1: per-row weighted sums (L2-resident stream).
// ---------------------------------------------------------------------------
__global__ void rowdot_kernel(const float* __restrict__ spikes,
                              const float* __restrict__ w,
                              const float* __restrict__ vrev,
                              int m, int n) {
    __shared__ float4 s_aw[128];
    __shared__ float4 s_wv[128];

    const int tid  = threadIdx.x;
    const int lane = tid & 31;
    const int wrp  = tid >> 5;
    const int nv4  = n >> 2;

    for (int j = tid; j < nv4; j += blockDim.x) {
        float4 wj = reinterpret_cast<const float4*>(w)[j];
        float4 vj = reinterpret_cast<const float4*>(vrev)[j];
        float4 aw = make_float4(fabsf(wj.x), fabsf(wj.y), fabsf(wj.z), fabsf(wj.w));
        s_aw[j] = aw;
        s_wv[j] = make_float4(__fmul_rn(vj.x, aw.x), __fmul_rn(vj.y, aw.y),
                              __fmul_rn(vj.z, aw.z), __fmul_rn(vj.w, aw.w));
    }
    __syncthreads();

    const int row = blockIdx.x * (blockDim.x >> 5) + wrp;
    if (row >= m) return;

    const float4* rp = reinterpret_cast<const float4*>(spikes + (size_t)row * n);
    float accg = 0.0f, acci = 0.0f;
    for (int j = lane; j < nv4; j += 32) {
        float4 s  = rp[j];
        float4 aw = s_aw[j];
        float4 wv = s_wv[j];
        accg = fmaf(s.x, aw.x, accg); accg = fmaf(s.y, aw.y, accg);
        accg = fmaf(s.z, aw.z, accg); accg = fmaf(s.w, aw.w, accg);
        acci = fmaf(s.x, wv.x, acci); acci = fmaf(s.y, wv.y, acci);
        acci = fmaf(s.z, wv.z, acci); acci = fmaf(s.w, wv.w, acci);
    }
    for (int j = (nv4 << 2) + lane; j < n; j += 32) {
        float aw = fabsf(w[j]);
        float sv = spikes[(size_t)row * n + j];
        accg = fmaf(sv, aw, accg);
        acci = fmaf(sv, __fmul_rn(vrev[j], aw), acci);
    }

    #pragma unroll
    for (int o = 16; o > 0; o >>= 1) {
        accg += __shfl_down_sync(0xffffffffu, accg, o);
        acci += __shfl_down_sync(0xffffffffu, acci, o);
    }
    if (lane == 0) {
        d_Sg[row] = accg;
        d_Si[row] = acci;
    }
}

// ---------------------------------------------------------------------------
// Kernel 2: chunk-local forced responses (exact ref op order within chunk).
// ---------------------------------------------------------------------------
__global__ void chains_kernel(int nchunk) {
    const int c    = blockIdx.x;
    const int lane = threadIdx.x;
    const int base = c * LC;
    const float d  = expf(-0.1f);

    float sg[8], si[8];
    #pragma unroll
    for (int q = 0; q < 8; ++q) {
        sg[q] = d_Sg[base + q * 32 + lane];
        si[q] = d_Si[base + q * 32 + lane];
    }

    float G = 0.0f, I = 0.0f;
    #pragma unroll
    for (int q = 0; q < 8; ++q) {
        float gs = 0.0f, is = 0.0f;
        #pragma unroll
        for (int k = 0; k < 32; ++k) {
            const float sgk = __shfl_sync(0xffffffffu, sg[q], k);
            const float sik = __shfl_sync(0xffffffffu, si[q], k);
            if (k == lane) { gs = G; is = I; }
            G = __fmul_rn(__fadd_rn(G, sgk), d);
            I = __fmul_rn(__fadd_rn(I, sik), d);
        }
        d_Gl[base + q * 32 + lane] = gs;
        d_Il[base + q * 32 + lane] = is;
    }
    if (lane == 0) { d_Gfe[c] = G; d_Ife[c] = I; }
}

// ---------------------------------------------------------------------------
// Kernel 3: chunk carries via affine warp-scan in double + P table.
//   map per chunk: H -> H*D + fe.  Compose f2∘f1: A=A1*A2, B=B1*A2+B2.
// ---------------------------------------------------------------------------
__global__ void carry_kernel(int nchunk) {     // 1 block x 64 threads
    const int tid = threadIdx.x;
    const double lg = log((double)expf(-0.1f));

    for (int j = tid; j < 256; j += 64) d_Ptab[j] = exp((double)j * lg);
    if (tid >= 32) return;

    const int    lane = tid;
    const double D    = exp((double)LC * lg);
    const int    per  = 7;                     // 32*7 = 224 >= nchunk(196)
    const int    c0   = lane * per;

    double A = 1.0, Bg = 0.0, Bi = 0.0;
    for (int q = 0; q < per; ++q) {
        const int c = c0 + q;
        const double feg = (c < nchunk) ? (double)d_Gfe[c] : 0.0;
        const double fei = (c < nchunk) ? (double)d_Ife[c] : 0.0;
        A  = A * D;
        Bg = Bg * D + feg;
        Bi = Bi * D + fei;
    }
    double Ai = A, BgI = Bg, BiI = Bi;
    for (int o = 1; o < 32; o <<= 1) {
        const double A1  = __shfl_up_sync(0xffffffffu, Ai, o);
        const double Bg1 = __shfl_up_sync(0xffffffffu, BgI, o);
        const double Bi1 = __shfl_up_sync(0xffffffffu, BiI, o);
        if (lane >= o) {
            BgI = Bg1 * Ai + BgI;
            BiI = Bi1 * Ai + BiI;
            Ai  = A1 * Ai;
        }
    }
    const double hgp = __shfl_up_sync(0xffffffffu, BgI, 1);
    const double hip = __shfl_up_sync(0xffffffffu, BiI, 1);
    double Hg = (lane > 0) ? hgp : 0.0;
    double Hi = (lane > 0) ? hip : 0.0;
    for (int q = 0; q < per; ++q) {
        const int c = c0 + q;
        if (c < nchunk) {
            d_GstD[c] = Hg; d_IstD[c] = Hi;
            Hg = Hg * D + (double)d_Gfe[c];
            Hi = Hi * D + (double)d_Ife[c];
        }
    }
}

// ---------------------------------------------------------------------------
// Kernel 4: recombine + emit (c,b); reset stitch state. Pad = identity step.
// ---------------------------------------------------------------------------
__global__ void combine_kernel(float* __restrict__ vtr, int m) {
    const int i = blockIdx.x * blockDim.x + threadIdx.x;
    if (i >= TOTAL) return;
    float2* cb = reinterpret_cast<float2*>(d_cb4);

    if (i < 16) { g_ent[0][i] = 0.0f; g_ent[1][i] = 0.0f; }
    if (i == 0) { g_bar_count = 0; g_bar_sense = 0; vtr[0] = 0.0f; }

    if (i >= m - 1) { cb[i] = make_float2(1.0f, 0.0f); return; }

    const int c   = i >> 8;
    const int off = i & 255;
    const double P = d_Ptab[off];

    const float G = (float)((double)d_Gl[i] + d_GstD[c] * P);
    const float I = (float)((double)d_Il[i] + d_IstD[c] * P);

    const float a  = __fmul_rn(0.001f, __fadd_rn(1.0f, G));
    const float cf = __fadd_rn(1.0f, -a);
    const float b  = __fmul_rn(0.001f, I);
    cb[i] = make_float2(cf, b);
}

// ---------------------------------------------------------------------------
// Kernel 5: wavefront stitch with merge detection. NSEG one-warp blocks.
// Sweep s: each block runs its segment from the current entry with the
// BIT-EXACT reference step order; it compares against its stored trajectory
// (in vtr) and stops at the first bitwise match (deterministic map => tails
// identical => stored exit exact continuation). Exactly NSEG sweeps =>
// sequential wavefront guarantees the exact answer; merges/skips make the
// later sweeps nearly free.
// ---------------------------------------------------------------------------
#define STEP(cc, bb, IDX) do {                                   \
    const float u_ = __fadd_rn(__fmul_rn(v, (cc)), (bb));        \
    v = (v < 1.0f) ? u_ : 0.0f;                                  \
    if ((IDX) == lane) vout = v;                                 \
} while (0)

#define GROUP8(Q) {                                              \
    const float4 n0_ = s4[pb + ((Q) + 1) * 4 + 0];               \
    const float4 n1_ = s4[pb + ((Q) + 1) * 4 + 1];               \
    const float4 n2_ = s4[pb + ((Q) + 1) * 4 + 2];               \
    const float4 n3_ = s4[pb + ((Q) + 1) * 4 + 3];               \
    STEP(p0.x, p0.y, (Q) * 8 + 0); STEP(p0.z, p0.w, (Q) * 8 + 1);\
    STEP(p1.x, p1.y, (Q) * 8 + 2); STEP(p1.z, p1.w, (Q) * 8 + 3);\
    STEP(p2.x, p2.y, (Q) * 8 + 4); STEP(p2.z, p2.w, (Q) * 8 + 5);\
    STEP(p3.x, p3.y, (Q) * 8 + 6); STEP(p3.z, p3.w, (Q) * 8 + 7);\
    p0 = n0_; p1 = n1_; p2 = n2_; p3 = n3_; }

__global__ void stitch_kernel(float* __restrict__ vtr, int m) {
    __shared__ float4 s4[SUB / 2 + 4];       // SUB float2 coeffs + prefetch pad

    const int k    = blockIdx.x;
    const int lane = threadIdx.x;
    const int base = k * LSEG;

    float    last_exit = 0.0f;
    unsigned prev_bits = 0xFFFFFFFFu;        // sentinel: always run sweep 0
    int      my_sense  = 0;

    for (int s = 0; s < NSEG; ++s) {
        const float entry = ((volatile float*)g_ent[s & 1])[k];
        const bool  run   = (__float_as_uint(entry) != prev_bits);
        prev_bits = __float_as_uint(entry);
        float exit_val = last_exit;

        if (run) {
            const bool have = (s > 0);       // stored trajectory exists
            float v = entry;
            int merged = 0;
            for (int sb = 0; sb < LSEG / SUB && !merged; ++sb) {
                const float4* gsrc = d_cb4 + (base + sb * SUB) / 2;
                for (int j = lane; j < SUB / 2 + 4; j += 32) s4[j] = gsrc[j];
                __syncwarp();
                for (int t = 0; t < SUB / 32 && !merged; ++t) {
                    const int i = base + sb * SUB + t * 32 + 1 + lane;
                    const bool ok = (i < m);
                    const float spec = (have && ok) ? vtr[i] : 0.0f;
                    float vout = 0.0f;
                    const int pb = t * 16;
                    float4 p0 = s4[pb], p1 = s4[pb + 1], p2 = s4[pb + 2], p3 = s4[pb + 3];
                    GROUP8(0); GROUP8(1); GROUP8(2); GROUP8(3);
                    const unsigned eq = __ballot_sync(0xffffffffu,
                        have && ok &&
                        (__float_as_uint(vout) == __float_as_uint(spec)));
                    if (ok) vtr[i] = vout;
                    if (eq) merged = 1;      // tails identical beyond match
                }
                __syncwarp();
            }
            exit_val = merged ? last_exit : v;
        }
        last_exit = exit_val;

        // publish exit for next sweep's parity buffer, then barrier
        my_sense ^= 1;
        if (lane == 0) {
            if (k + 1 < NSEG) ((volatile float*)g_ent[(s + 1) & 1])[k + 1] = exit_val;
            __threadfence();
            if (atomicAdd(&g_bar_count, 1) == NSEG - 1) {
                g_bar_count = 0;
                __threadfence();
                g_bar_sense = my_sense;
            } else {
                while (*((volatile int*)&g_bar_sense) != my_sense) { }
            }
            __threadfence();
        }
        __syncwarp();
    }
}

// ---------------------------------------------------------------------------
extern "C" void kernel_launch(void* const* d_in, const int* in_sizes, int n_in,
                              void* d_out, int out_size) {
    const float* spikes = (const float*)d_in[0];
    const float* w      = (const float*)d_in[1];
    const float* vrev   = (const float*)d_in[2];
    float*       vtr    = (float*)d_out;

    const int n = in_sizes[1];                       // 500
    const int m = in_sizes[0] / n;                   // 50000
    const int nchunk = (m + LC - 1) / LC;            // 196

    rowdot_kernel<<<(m + 7) / 8, 256>>>(spikes, w, vrev, m, n);
    chains_kernel<<<nchunk, 32>>>(nchunk);
    carry_kernel<<<1, 64>>>(nchunk);
    combine_kernel<<<(TOTAL + 255) / 256, 256>>>(vtr, m);
    stitch_kernel<<<NSEG, 32>>>(vtr, m);
}

// round 8
// speedup vs baseline: 1.1302x; 1.1302x over previous
#include <cuda_runtime.h>
#include <math.h>

// ---------------------------------------------------------------------------
// Static device scratch (allocation-free rule). Zero-initialized at load.
// ---------------------------------------------------------------------------
#define MAX_M 50432
#define LC    256                  // chunk length for linear G/I scans
#define LSEG  3200                 // stitch segment length
#define NSEG  16                   // segments: 16*3200 = 51200 >= m-1
#define TOTAL (NSEG * LSEG)
#define PRED_SWEEPS 3

__device__ float  d_Sg[MAX_M];
__device__ float  d_Si[MAX_M];
__device__ float  d_Gl[MAX_M];
__device__ float  d_Il[MAX_M];
__device__ float  d_Gfe[256];
__device__ float  d_Ife[256];
__device__ double d_GstD[256];
__device__ double d_IstD[256];
__device__ double d_Ptab[256];
__device__ float4 d_cb4[(TOTAL + 16) / 2]; // float2 view: per-step (c, b)
__device__ float  g_ent[2][32];            // segment entries, ping-pong
__device__ int    g_flag[2];               // "all blocks skipped" flags
__device__ int    g_bar_count;
__device__ int    g_bar_sense;

// ---------------------------------------------------------------------------
// Kernel 1: per-row weighted sums (L2-resident stream).
// ---------------------------------------------------------------------------
__global__ void rowdot_kernel(const float* __restrict__ spikes,
                              const float* __restrict__ w,
                              const float* __restrict__ vrev,
                              int m, int n) {
    __shared__ float4 s_aw[128];
    __shared__ float4 s_wv[128];

    const int tid  = threadIdx.x;
    const int lane = tid & 31;
    const int wrp  = tid >> 5;
    const int nv4  = n >> 2;

    for (int j = tid; j < nv4; j += blockDim.x) {
        float4 wj = reinterpret_cast<const float4*>(w)[j];
        float4 vj = reinterpret_cast<const float4*>(vrev)[j];
        float4 aw = make_float4(fabsf(wj.x), fabsf(wj.y), fabsf(wj.z), fabsf(wj.w));
        s_aw[j] = aw;
        s_wv[j] = make_float4(__fmul_rn(vj.x, aw.x), __fmul_rn(vj.y, aw.y),
                              __fmul_rn(vj.z, aw.z), __fmul_rn(vj.w, aw.w));
    }
    __syncthreads();

    const int row = blockIdx.x * (blockDim.x >> 5) + wrp;
    if (row >= m) return;

    const float4* rp = reinterpret_cast<const float4*>(spikes + (size_t)row * n);
    float accg = 0.0f, acci = 0.0f;
    for (int j = lane; j < nv4; j += 32) {
        float4 s  = rp[j];
        float4 aw = s_aw[j];
        float4 wv = s_wv[j];
        accg = fmaf(s.x, aw.x, accg); accg = fmaf(s.y, aw.y, accg);
        accg = fmaf(s.z, aw.z, accg); accg = fmaf(s.w, aw.w, accg);
        acci = fmaf(s.x, wv.x, acci); acci = fmaf(s.y, wv.y, acci);
        acci = fmaf(s.z, wv.z, acci); acci = fmaf(s.w, wv.w, acci);
    }
    for (int j = (nv4 << 2) + lane; j < n; j += 32) {
        float aw = fabsf(w[j]);
        float sv = spikes[(size_t)row * n + j];
        accg = fmaf(sv, aw, accg);
        acci = fmaf(sv, __fmul_rn(vrev[j], aw), acci);
    }

    #pragma unroll
    for (int o = 16; o > 0; o >>= 1) {
        accg += __shfl_down_sync(0xffffffffu, accg, o);
        acci += __shfl_down_sync(0xffffffffu, acci, o);
    }
    if (lane == 0) {
        d_Sg[row] = accg;
        d_Si[row] = acci;
    }
}

// ---------------------------------------------------------------------------
// Kernel 2: chunk-local forced responses (exact ref op order within chunk).
// ---------------------------------------------------------------------------
__global__ void chains_kernel(int nchunk) {
    const int c    = blockIdx.x;
    const int lane = threadIdx.x;
    const int base = c * LC;
    const float d  = expf(-0.1f);

    float sg[8], si[8];
    #pragma unroll
    for (int q = 0; q < 8; ++q) {
        sg[q] = d_Sg[base + q * 32 + lane];
        si[q] = d_Si[base + q * 32 + lane];
    }

    float G = 0.0f, I = 0.0f;
    #pragma unroll
    for (int q = 0; q < 8; ++q) {
        float gs = 0.0f, is = 0.0f;
        #pragma unroll
        for (int k = 0; k < 32; ++k) {
            const float sgk = __shfl_sync(0xffffffffu, sg[q], k);
            const float sik = __shfl_sync(0xffffffffu, si[q], k);
            if (k == lane) { gs = G; is = I; }
            G = __fmul_rn(__fadd_rn(G, sgk), d);
            I = __fmul_rn(__fadd_rn(I, sik), d);
        }
        d_Gl[base + q * 32 + lane] = gs;
        d_Il[base + q * 32 + lane] = is;
    }
    if (lane == 0) { d_Gfe[c] = G; d_Ife[c] = I; }
}

// ---------------------------------------------------------------------------
// Kernel 3: chunk carries via affine warp-scan in double + P table.
// ---------------------------------------------------------------------------
__global__ void carry_kernel(int nchunk) {     // 1 block x 64 threads
    const int tid = threadIdx.x;
    const double lg = log((double)expf(-0.1f));

    for (int j = tid; j < 256; j += 64) d_Ptab[j] = exp((double)j * lg);
    if (tid >= 32) return;

    const int    lane = tid;
    const double D    = exp((double)LC * lg);
    const int    per  = 7;                     // 32*7 = 224 >= nchunk(196)
    const int    c0   = lane * per;

    double A = 1.0, Bg = 0.0, Bi = 0.0;
    for (int q = 0; q < per; ++q) {
        const int c = c0 + q;
        const double feg = (c < nchunk) ? (double)d_Gfe[c] : 0.0;
        const double fei = (c < nchunk) ? (double)d_Ife[c] : 0.0;
        A  = A * D;
        Bg = Bg * D + feg;
        Bi = Bi * D + fei;
    }
    double Ai = A, BgI = Bg, BiI = Bi;
    for (int o = 1; o < 32; o <<= 1) {
        const double A1  = __shfl_up_sync(0xffffffffu, Ai, o);
        const double Bg1 = __shfl_up_sync(0xffffffffu, BgI, o);
        const double Bi1 = __shfl_up_sync(0xffffffffu, BiI, o);
        if (lane >= o) {
            BgI = Bg1 * Ai + BgI;
            BiI = Bi1 * Ai + BiI;
            Ai  = A1 * Ai;
        }
    }
    const double hgp = __shfl_up_sync(0xffffffffu, BgI, 1);
    const double hip = __shfl_up_sync(0xffffffffu, BiI, 1);
    double Hg = (lane > 0) ? hgp : 0.0;
    double Hi = (lane > 0) ? hip : 0.0;
    for (int q = 0; q < per; ++q) {
        const int c = c0 + q;
        if (c < nchunk) {
            d_GstD[c] = Hg; d_IstD[c] = Hi;
            Hg = Hg * D + (double)d_Gfe[c];
            Hi = Hi * D + (double)d_Ife[c];
        }
    }
}

// ---------------------------------------------------------------------------
// Kernel 4: recombine + emit (c,b); reset solver state. Pad = identity step.
// ---------------------------------------------------------------------------
__global__ void combine_kernel(float* __restrict__ vtr, int m) {
    const int i = blockIdx.x * blockDim.x + threadIdx.x;
    if (i >= TOTAL) return;
    float2* cb = reinterpret_cast<float2*>(d_cb4);

    if (i < 32) { g_ent[0][i] = 0.0f; g_ent[1][i] = 0.0f; }
    if (i == 0) {
        g_flag[0] = 1; g_flag[1] = 1;
        g_bar_count = 0; g_bar_sense = 0;
        vtr[0] = 0.0f;
    }

    if (i >= m - 1) { cb[i] = make_float2(1.0f, 0.0f); return; }

    const int c   = i >> 8;
    const int off = i & 255;
    const double P = d_Ptab[off];

    const float G = (float)((double)d_Gl[i] + d_GstD[c] * P);
    const float I = (float)((double)d_Il[i] + d_IstD[c] * P);

    const float a  = __fmul_rn(0.001f, __fadd_rn(1.0f, G));
    const float cf = __fadd_rn(1.0f, -a);
    const float b  = __fmul_rn(0.001f, I);
    cb[i] = make_float2(cf, b);
}

// ---------------------------------------------------------------------------
// Kernel 5: predictor + exact wavefront stitch, one persistent launch.
//
// Phase P (3 sweeps): value-space Jacobi with FAST fused steps
// (fma.rn + setp||selp ~ 8 cyc/step). Drives segment-entry errors from
// O(0.5) down to ~1e-6 so threshold crossings align with the exact run.
//
// Phase E (<= NSEG sweeps): bit-exact replays (mul.rn -> add.rn, setp||selp
// ~ 12 cyc/step). A block skips if its entry bits repeat; otherwise it runs
// until its trajectory bitwise-matches the stored one (aligned reset -> both
// exactly 0 -> deterministic map -> identical tails) and merges. All-skip
// sweep => bitwise fixed point anchored at e0=0 => exact sequential answer.
// Cap of NSEG sweeps = sequential wavefront guarantee.
// ---------------------------------------------------------------------------
#define PSTEP(cc, bb) do {                                        \
    float _vn;                                                    \
    asm("{\n\t"                                                   \
        ".reg .pred p;\n\t"                                       \
        ".reg .f32 t;\n\t"                                        \
        "fma.rn.f32 t, %1, %2, %3;\n\t"                           \
        "setp.lt.f32 p, %1, 0f3F800000;\n\t"                      \
        "selp.f32 %0, t, 0f00000000, p;\n\t"                      \
        "}" : "=f"(_vn) : "f"(v), "f"(cc), "f"(bb));              \
    v = _vn;                                                      \
} while (0)

#define STEPX(cc, bb, IDX) do {                                   \
    float _vn;                                                    \
    asm("{\n\t"                                                   \
        ".reg .pred p;\n\t"                                       \
        ".reg .f32 t;\n\t"                                        \
        "mul.rn.f32 t, %1, %2;\n\t"                               \
        "add.rn.f32 t, t, %3;\n\t"                                \
        "setp.lt.f32 p, %1, 0f3F800000;\n\t"                      \
        "selp.f32 %0, t, 0f00000000, p;\n\t"                      \
        "}" : "=f"(_vn) : "f"(v), "f"(cc), "f"(bb));              \
    v = _vn;                                                      \
    if ((IDX) == lane) vout = v;                                  \
} while (0)

#define GROUP8X(Q) {                                              \
    const float4 n0_ = s4[pb + ((Q) + 1) * 4 + 0];                \
    const float4 n1_ = s4[pb + ((Q) + 1) * 4 + 1];                \
    const float4 n2_ = s4[pb + ((Q) + 1) * 4 + 2];                \
    const float4 n3_ = s4[pb + ((Q) + 1) * 4 + 3];                \
    STEPX(p0.x, p0.y, (Q)*8 + 0); STEPX(p0.z, p0.w, (Q)*8 + 1);   \
    STEPX(p1.x, p1.y, (Q)*8 + 2); STEPX(p1.z, p1.w, (Q)*8 + 3);   \
    STEPX(p2.x, p2.y, (Q)*8 + 4); STEPX(p2.z, p2.w, (Q)*8 + 5);   \
    STEPX(p3.x, p3.y, (Q)*8 + 6); STEPX(p3.z, p3.w, (Q)*8 + 7);   \
    p0 = n0_; p1 = n1_; p2 = n2_; p3 = n3_; }

__device__ __forceinline__ void grid_barrier(int lane, int my_sense, int nxt_par) {
    if (lane == 0) {
        __threadfence();
        if (atomicAdd(&g_bar_count, 1) == NSEG - 1) {
            g_bar_count = 0;
            g_flag[nxt_par] = 1;               // arm skip-flag for next sweep
            __threadfence();
            g_bar_sense = my_sense;            // release
        } else {
            while (*((volatile int*)&g_bar_sense) != my_sense) { }
        }
        __threadfence();
    }
    __syncwarp();
}

__global__ void solve_kernel(float* __restrict__ vtr, int m) {
    __shared__ float4 s4[LSEG / 2 + 4];

    const int k    = blockIdx.x;
    const int lane = threadIdx.x;
    const int base = k * LSEG;

    // stage this segment's (c,b) coefficients once
    const float4* gsrc = d_cb4 + base / 2;
    for (int j = lane; j < LSEG / 2 + 4; j += 32) s4[j] = gsrc[j];
    __syncwarp();

    int par = 0, my_sense = 0;

    // ---------------- Phase P: value predictor sweeps -----------------
    for (int s = 0; s < PRED_SWEEPS; ++s) {
        float v = ((volatile float*)g_ent[par])[k];
        for (int t = 0; t < LSEG / 32; ++t) {
            const int pb = t * 16;
            #pragma unroll
            for (int q = 0; q < 16; ++q) {
                const float4 f = s4[pb + q];
                PSTEP(f.x, f.y);
                PSTEP(f.z, f.w);
            }
        }
        my_sense ^= 1;
        if (lane == 0) ((volatile float*)g_ent[par ^ 1])[k + 1] = v;
        grid_barrier(lane, my_sense, par ^ 1);
        par ^= 1;
    }

    // ---------------- Phase E: exact sweeps with merge/skip -----------
    unsigned prev_bits = 0u;
    float    last_exit = 0.0f;

    for (int s = 0; s < NSEG; ++s) {
        const float entry = ((volatile float*)g_ent[par])[k];
        const bool  run   = (s == 0) ||
                            (__float_as_uint(entry) != prev_bits);
        prev_bits = __float_as_uint(entry);
        float exitv = last_exit;

        if (run) {
            if (lane == 0) atomicExch(&g_flag[par], 0);   // not all-skip
            const bool have = (s > 0);
            float v = entry;
            int merged = 0;
            for (int t = 0; t < LSEG / 32 && !merged; ++t) {
                const int  i  = base + t * 32 + 1 + lane;
                const bool ok = (i < m);
                const float spec = (have && ok) ? vtr[i] : 0.0f;
                float vout = 0.0f;
                const int pb = t * 16;
                float4 p0 = s4[pb], p1 = s4[pb+1], p2 = s4[pb+2], p3 = s4[pb+3];
                GROUP8X(0); GROUP8X(1); GROUP8X(2); GROUP8X(3);
                const unsigned eq = __ballot_sync(0xffffffffu,
                    have && ok &&
                    (__float_as_uint(vout) == __float_as_uint(spec)));
                if (ok) vtr[i] = vout;
                if (eq) merged = 1;            // stored tail is exact cont.
            }
            exitv = merged ? last_exit : v;
        }
        last_exit = exitv;

        my_sense ^= 1;
        if (lane == 0) ((volatile float*)g_ent[par ^ 1])[k + 1] = exitv;
        grid_barrier(lane, my_sense, par ^ 1);

        int fl = 0;
        if (lane == 0) fl = *((volatile int*)&g_flag[par]);
        fl = __shfl_sync(0xffffffffu, fl, 0);
        par ^= 1;
        if (s > 0 && fl) break;                // bitwise fixed point => exact
    }
}

// ---------------------------------------------------------------------------
extern "C" void kernel_launch(void* const* d_in, const int* in_sizes, int n_in,
                              void* d_out, int out_size) {
    const float* spikes = (const float*)d_in[0];
    const float* w      = (const float*)d_in[1];
    const float* vrev   = (const float*)d_in[2];
    float*       vtr    = (float*)d_out;

    const int n = in_sizes[1];                       // 500
    const int m = in_sizes[0] / n;                   // 50000
    const int nchunk = (m + LC - 1) / LC;            // 196

    rowdot_kernel<<<(m + 7) / 8, 256>>>(spikes, w, vrev, m, n);
    chains_kernel<<<nchunk, 32>>>(nchunk);
    carry_kernel<<<1, 64>>>(nchunk);
    combine_kernel<<<(TOTAL + 255) / 256, 256>>>(vtr, m);
    solve_kernel<<<NSEG, 32>>>(vtr, m);
}